// round 1
// baseline (speedup 1.0000x reference)
#include <cuda_runtime.h>
#include <cuda_bf16.h>

#define Dm 2048
#define Bm 256
#define Kc 4

// scratch for intermediate y = Cg * conv_out  (no cudaMalloc allowed)
__device__ float g_y[Bm * Dm];

// ---------------------------------------------------------------------------
// Kernel A: fused GEMM1 (x @ w1^T, all 3 gates) + gating + cache roll/scatter
//           + depthwise conv + C-gate. Writes state -> d_out, y -> g_y.
// Block: 64 (b) x 64 (d) tile, 256 threads, 4x4 micro-tile per thread, 3 gates.
// ---------------------------------------------------------------------------
__global__ __launch_bounds__(256) void k_gemm1_fused(
    const float* __restrict__ x,          // [B, 1, D]
    const float* __restrict__ conv_cache, // [B, D, K]
    const float* __restrict__ w1,         // [3D, D]
    const float* __restrict__ conv_w,     // [D, K]
    const int*   __restrict__ pos_ids,    // [1]
    float* __restrict__ out_state)        // [B, D, K]
{
    __shared__ float xs[64][17];
    __shared__ float ws[3][64][17];

    const int tid = threadIdx.x;
    const int tx = tid & 15;        // d-group
    const int ty = tid >> 4;        // b-group
    const int dBase = blockIdx.x * 64;
    const int bBase = blockIdx.y * 64;

    float accB[4][4] = {};
    float accC[4][4] = {};
    float accX[4][4] = {};

    for (int kk = 0; kk < Dm; kk += 16) {
        // x tile: 64x16 = 1024 elems, 4 per thread
        #pragma unroll
        for (int i = 0; i < 4; i++) {
            int t = tid + i * 256;
            int r = t >> 4, c = t & 15;
            xs[r][c] = x[(bBase + r) * Dm + kk + c];
        }
        // w1 tiles (3 gates): 3x64x16 = 3072 elems, 12 per thread
        #pragma unroll
        for (int i = 0; i < 12; i++) {
            int t = tid + i * 256;
            int g = t >> 10;
            int rem = t & 1023;
            int r = rem >> 4, c = rem & 15;
            ws[g][r][c] = w1[(g * Dm + dBase + r) * Dm + kk + c];
        }
        __syncthreads();

        #pragma unroll
        for (int k = 0; k < 16; k++) {
            float a[4], bB[4], bC[4], bX[4];
            #pragma unroll
            for (int i = 0; i < 4; i++) a[i] = xs[ty * 4 + i][k];
            #pragma unroll
            for (int j = 0; j < 4; j++) {
                bB[j] = ws[0][tx * 4 + j][k];
                bC[j] = ws[1][tx * 4 + j][k];
                bX[j] = ws[2][tx * 4 + j][k];
            }
            #pragma unroll
            for (int i = 0; i < 4; i++)
                #pragma unroll
                for (int j = 0; j < 4; j++) {
                    accB[i][j] = fmaf(a[i], bB[j], accB[i][j]);
                    accC[i][j] = fmaf(a[i], bC[j], accC[i][j]);
                    accX[i][j] = fmaf(a[i], bX[j], accX[i][j]);
                }
        }
        __syncthreads();
    }

    // epilogue: Bx = Bg*xg; state = roll(cache,-1) with state[pos]=Bx;
    // conv_out = sum(state*conv_w); y = Cg*conv_out
    int pos = pos_ids[0];
    pos = min(max(pos, 0), Kc - 1);

    #pragma unroll
    for (int i = 0; i < 4; i++) {
        const int b = bBase + ty * 4 + i;
        #pragma unroll
        for (int j = 0; j < 4; j++) {
            const int d = dBase + tx * 4 + j;
            const float Bx = accB[i][j] * accX[i][j];

            const float4 ccv = *reinterpret_cast<const float4*>(
                conv_cache + ((size_t)(b * Dm + d)) * Kc);
            float cc[Kc] = {ccv.x, ccv.y, ccv.z, ccv.w};
            float st[Kc];
            #pragma unroll
            for (int q = 0; q < Kc; q++) st[q] = cc[(q + 1) & (Kc - 1)];
            st[pos] = Bx;

            const float4 cwv = *reinterpret_cast<const float4*>(conv_w + d * Kc);
            float co = st[0] * cwv.x + st[1] * cwv.y + st[2] * cwv.z + st[3] * cwv.w;

            g_y[b * Dm + d] = accC[i][j] * co;

            float4 stv = make_float4(st[0], st[1], st[2], st[3]);
            *reinterpret_cast<float4*>(out_state + ((size_t)(b * Dm + d)) * Kc) = stv;
        }
    }
}

// ---------------------------------------------------------------------------
// Kernel B: out = y @ w2^T   ([256,2048] x [2048,2048]^T -> [256,2048])
// ---------------------------------------------------------------------------
__global__ __launch_bounds__(256) void k_gemm2(
    const float* __restrict__ w2,  // [D, D]
    float* __restrict__ out)       // [B, 1, D]
{
    __shared__ float ys[64][17];
    __shared__ float ws[64][17];

    const int tid = threadIdx.x;
    const int tx = tid & 15;
    const int ty = tid >> 4;
    const int eBase = blockIdx.x * 64;
    const int bBase = blockIdx.y * 64;

    float acc[4][4] = {};

    for (int kk = 0; kk < Dm; kk += 16) {
        #pragma unroll
        for (int i = 0; i < 4; i++) {
            int t = tid + i * 256;
            int r = t >> 4, c = t & 15;
            ys[r][c] = g_y[(bBase + r) * Dm + kk + c];
            ws[r][c] = w2[(eBase + r) * Dm + kk + c];
        }
        __syncthreads();

        #pragma unroll
        for (int k = 0; k < 16; k++) {
            float a[4], bb[4];
            #pragma unroll
            for (int i = 0; i < 4; i++) a[i] = ys[ty * 4 + i][k];
            #pragma unroll
            for (int j = 0; j < 4; j++) bb[j] = ws[tx * 4 + j][k];
            #pragma unroll
            for (int i = 0; i < 4; i++)
                #pragma unroll
                for (int j = 0; j < 4; j++)
                    acc[i][j] = fmaf(a[i], bb[j], acc[i][j]);
        }
        __syncthreads();
    }

    #pragma unroll
    for (int i = 0; i < 4; i++) {
        const int b = bBase + ty * 4 + i;
        #pragma unroll
        for (int j = 0; j < 4; j++) {
            const int e = eBase + tx * 4 + j;
            out[b * Dm + e] = acc[i][j];
        }
    }
}

extern "C" void kernel_launch(void* const* d_in, const int* in_sizes, int n_in,
                              void* d_out, int out_size) {
    const float* x          = (const float*)d_in[0];
    const float* conv_cache = (const float*)d_in[1];
    const float* w1         = (const float*)d_in[2];
    const float* w2         = (const float*)d_in[3];
    const float* conv_w     = (const float*)d_in[4];
    const int*   pos_ids    = (const int*)d_in[5];

    float* out       = (float*)d_out;            // [B,1,D] = 524288 floats
    float* out_state = out + (size_t)Bm * Dm;    // [B,D,K] = 2097152 floats

    dim3 grid1(Dm / 64, Bm / 64);  // (32, 4)
    k_gemm1_fused<<<grid1, 256>>>(x, conv_cache, w1, conv_w, pos_ids, out_state);

    dim3 grid2(Dm / 64, Bm / 64);  // (32, 4)
    k_gemm2<<<grid2, 256>>>(w2, out);
}

// round 3
// speedup vs baseline: 2.7676x; 2.7676x over previous
#include <cuda_runtime.h>
#include <cstdint>

#define Dm 2048
#define Bm 256

// scratch (no cudaMalloc allowed)
__device__ float g_bcx[Bm * 3 * Dm];   // GEMM1 output [256, 6144]
__device__ float g_y[Bm * Dm];         // gated intermediate [256, 2048]

__device__ __forceinline__ uint32_t f2tf32(float f) {
    uint32_t r; asm("cvt.rna.tf32.f32 %0, %1;" : "=r"(r) : "f"(f)); return r;
}

__device__ __forceinline__ void mma8(float* d, const uint32_t* a, const uint32_t* b) {
    asm volatile(
        "mma.sync.aligned.m16n8k8.row.col.f32.tf32.tf32.f32 "
        "{%0,%1,%2,%3}, {%4,%5,%6,%7}, {%8,%9}, {%0,%1,%2,%3};"
        : "+f"(d[0]), "+f"(d[1]), "+f"(d[2]), "+f"(d[3])
        : "r"(a[0]), "r"(a[1]), "r"(a[2]), "r"(a[3]), "r"(b[0]), "r"(b[1]));
}

// ---------------------------------------------------------------------------
// tf32 tensor-core GEMM: C[M,N] = A[M,K] @ Bw[N,K]^T  (fp32 in/out)
// Smem: row-major, K padded 32->36 (stride%32==4 -> conflict-free frag LDS).
// ---------------------------------------------------------------------------
template <int BM, int BN, int WM, int WN, int THREADS>
__global__ __launch_bounds__(THREADS) void k_mma_tf32(
    const float* __restrict__ A, const float* __restrict__ Bw,
    float* __restrict__ C, int lda, int ldb, int ldc)
{
    extern __shared__ uint32_t sm[];
    constexpr int SA = BM * 36, SB = BN * 36, STG = SA + SB;
    constexpr int MT = WM / 16, NT = WN / 8;
    constexpr int WARPS_N = BN / WN;
    constexpr int NLD_A = BM * 8 / THREADS;   // float4 per thread for A
    constexpr int NLD_B = BN * 8 / THREADS;
    constexpr int NSTG = Dm / 32;             // 64

    const int tid = threadIdx.x;
    const int wid = tid >> 5, lane = tid & 31;
    const int g = lane >> 2, c = lane & 3;
    const int wm = (wid / WARPS_N) * WM, wn = (wid % WARPS_N) * WN;
    const int mBase = blockIdx.y * BM, nBase = blockIdx.x * BN;

    float acc[MT][NT][4] = {};
    float4 ra[NLD_A], rb[NLD_B];

    auto ldg = [&](int k0) {
        #pragma unroll
        for (int i = 0; i < NLD_A; i++) {
            int idx = tid + i * THREADS; int m = idx >> 3, k4 = idx & 7;
            ra[i] = *reinterpret_cast<const float4*>(
                &A[(size_t)(mBase + m) * lda + k0 + k4 * 4]);
        }
        #pragma unroll
        for (int i = 0; i < NLD_B; i++) {
            int idx = tid + i * THREADS; int n = idx >> 3, k4 = idx & 7;
            rb[i] = *reinterpret_cast<const float4*>(
                &Bw[(size_t)(nBase + n) * ldb + k0 + k4 * 4]);
        }
    };
    auto sts = [&](int buf) {
        uint32_t* Ab = sm + buf * STG;
        uint32_t* Bb = Ab + SA;
        #pragma unroll
        for (int i = 0; i < NLD_A; i++) {
            int idx = tid + i * THREADS; int m = idx >> 3, k4 = idx & 7;
            uint4 u = make_uint4(f2tf32(ra[i].x), f2tf32(ra[i].y),
                                 f2tf32(ra[i].z), f2tf32(ra[i].w));
            *reinterpret_cast<uint4*>(&Ab[m * 36 + k4 * 4]) = u;
        }
        #pragma unroll
        for (int i = 0; i < NLD_B; i++) {
            int idx = tid + i * THREADS; int n = idx >> 3, k4 = idx & 7;
            uint4 u = make_uint4(f2tf32(rb[i].x), f2tf32(rb[i].y),
                                 f2tf32(rb[i].z), f2tf32(rb[i].w));
            *reinterpret_cast<uint4*>(&Bb[n * 36 + k4 * 4]) = u;
        }
    };

    ldg(0); sts(0); __syncthreads();
    int buf = 0;

    for (int s = 0; s < NSTG; s++) {
        if (s + 1 < NSTG) ldg((s + 1) * 32);

        const uint32_t* Ab = sm + buf * STG;
        const uint32_t* Bb = Ab + SA;
        #pragma unroll
        for (int step = 0; step < 4; step++) {
            const int kk = step * 8;
            uint32_t af[MT][4], bf[NT][2];
            #pragma unroll
            for (int mt = 0; mt < MT; mt++) {
                int m0 = wm + mt * 16 + g;
                af[mt][0] = Ab[m0 * 36 + kk + c];
                af[mt][1] = Ab[(m0 + 8) * 36 + kk + c];
                af[mt][2] = Ab[m0 * 36 + kk + c + 4];
                af[mt][3] = Ab[(m0 + 8) * 36 + kk + c + 4];
            }
            #pragma unroll
            for (int nt = 0; nt < NT; nt++) {
                int n0 = wn + nt * 8 + g;
                bf[nt][0] = Bb[n0 * 36 + kk + c];
                bf[nt][1] = Bb[n0 * 36 + kk + c + 4];
            }
            #pragma unroll
            for (int mt = 0; mt < MT; mt++)
                #pragma unroll
                for (int nt = 0; nt < NT; nt++)
                    mma8(acc[mt][nt], af[mt], bf[nt]);
        }

        if (s + 1 < NSTG) sts(buf ^ 1);
        __syncthreads();
        buf ^= 1;
    }

    // epilogue: c0,c1 -> (row, 2c), c2,c3 -> (row+8, 2c)
    #pragma unroll
    for (int mt = 0; mt < MT; mt++) {
        const int row = mBase + wm + mt * 16 + g;
        #pragma unroll
        for (int nt = 0; nt < NT; nt++) {
            const int col = nBase + wn + nt * 8 + 2 * c;
            *reinterpret_cast<float2*>(&C[(size_t)row * ldc + col]) =
                make_float2(acc[mt][nt][0], acc[mt][nt][1]);
            *reinterpret_cast<float2*>(&C[(size_t)(row + 8) * ldc + col]) =
                make_float2(acc[mt][nt][2], acc[mt][nt][3]);
        }
    }
}

// ---------------------------------------------------------------------------
// Elementwise: gates + cache roll/scatter + depthwise conv + C-gate
// ---------------------------------------------------------------------------
__global__ __launch_bounds__(256) void k_elem(
    const float* __restrict__ conv_cache, const float* __restrict__ conv_w,
    const int* __restrict__ pos_ids, float* __restrict__ out_state)
{
    const int idx = blockIdx.x * 256 + threadIdx.x;   // b*2048 + d
    const int b = idx >> 11, d = idx & 2047;

    const float Bg = g_bcx[(size_t)b * 6144 + d];
    const float Cg = g_bcx[(size_t)b * 6144 + 2048 + d];
    const float xg = g_bcx[(size_t)b * 6144 + 4096 + d];
    const float Bx = Bg * xg;

    int pos = pos_ids[0];
    pos = min(max(pos, 0), 3);

    const float4 cc = *reinterpret_cast<const float4*>(conv_cache + (size_t)idx * 4);
    float st[4] = {cc.y, cc.z, cc.w, cc.x};   // roll left by 1
    st[pos] = Bx;

    const float4 cw = *reinterpret_cast<const float4*>(conv_w + (size_t)d * 4);
    const float co = st[0] * cw.x + st[1] * cw.y + st[2] * cw.z + st[3] * cw.w;

    g_y[idx] = Cg * co;
    *reinterpret_cast<float4*>(out_state + (size_t)idx * 4) =
        make_float4(st[0], st[1], st[2], st[3]);
}

// ---------------------------------------------------------------------------
extern "C" void kernel_launch(void* const* d_in, const int* in_sizes, int n_in,
                              void* d_out, int out_size) {
    const float* x          = (const float*)d_in[0];
    const float* conv_cache = (const float*)d_in[1];
    const float* w1         = (const float*)d_in[2];
    const float* w2         = (const float*)d_in[3];
    const float* conv_w     = (const float*)d_in[4];
    const int*   pos_ids    = (const int*)d_in[5];

    float* out       = (float*)d_out;            // [B,1,D]
    float* out_state = out + (size_t)Bm * Dm;    // [B,D,K]

    float* bcx = nullptr, *y = nullptr;
    cudaGetSymbolAddress((void**)&bcx, g_bcx);
    cudaGetSymbolAddress((void**)&y, g_y);

    constexpr int SMEM1 = 2 * (128 + 128) * 36 * 4;   // 73728 B
    constexpr int SMEM2 = 2 * (64 + 64) * 36 * 4;     // 36864 B
    cudaFuncSetAttribute((const void*)k_mma_tf32<128, 128, 64, 32, 256>,
                         cudaFuncAttributeMaxDynamicSharedMemorySize, SMEM1);

    // GEMM1: BCx[256, 6144] = x[256,2048] @ w1[6144,2048]^T
    k_mma_tf32<128, 128, 64, 32, 256><<<dim3(3 * Dm / 128, Bm / 128), 256, SMEM1>>>(
        x, w1, bcx, Dm, Dm, 3 * Dm);

    // gating + conv + state scatter
    k_elem<<<(Bm * Dm) / 256, 256>>>(conv_cache, conv_w, pos_ids, out_state);

    // GEMM2: out[256, 2048] = y[256,2048] @ w2[2048,2048]^T
    k_mma_tf32<64, 64, 32, 32, 128><<<dim3(Dm / 64, Bm / 64), 128, SMEM2>>>(
        y, w2, out, Dm, Dm, Dm);
}

// round 4
// speedup vs baseline: 2.9772x; 1.0758x over previous
#include <cuda_runtime.h>
#include <cstdint>

#define Dm 2048
#define Bm 256

// scratch (no cudaMalloc allowed)
__device__ float g_bcx[Bm * 3 * Dm];   // GEMM1 output [256, 6144]
__device__ float g_y[Bm * Dm];         // gated intermediate [256, 2048]

__device__ __forceinline__ uint32_t f2tf32(float f) {
    uint32_t r; asm("cvt.rna.tf32.f32 %0, %1;" : "=r"(r) : "f"(f)); return r;
}

__device__ __forceinline__ void mma8(float* d, const uint32_t* a, const uint32_t* b) {
    asm volatile(
        "mma.sync.aligned.m16n8k8.row.col.f32.tf32.tf32.f32 "
        "{%0,%1,%2,%3}, {%4,%5,%6,%7}, {%8,%9}, {%0,%1,%2,%3};"
        : "+f"(d[0]), "+f"(d[1]), "+f"(d[2]), "+f"(d[3])
        : "r"(a[0]), "r"(a[1]), "r"(a[2]), "r"(a[3]), "r"(b[0]), "r"(b[1]));
}

__device__ __forceinline__ void cp16(uint32_t saddr, const void* gptr) {
    asm volatile("cp.async.cg.shared.global [%0], [%1], 16;"
                 :: "r"(saddr), "l"(gptr));
}
#define CP_COMMIT() asm volatile("cp.async.commit_group;" ::: "memory")
#define CP_WAIT(n)  asm volatile("cp.async.wait_group %0;" :: "n"(n) : "memory")

// ---------------------------------------------------------------------------
// tf32 tensor-core GEMM: C[M,N] = A[M,K] @ Bw[N,K]^T  (fp32 in/out)
// 3-stage cp.async pipeline; smem holds raw fp32 (rows of 32 padded to 36
// words -> conflict-free fragment LDS); cvt.rna.tf32 applied post-LDS.
// ---------------------------------------------------------------------------
template <int BM, int BN, int WM, int WN, int THREADS, int STAGES>
__global__ __launch_bounds__(THREADS, 2) void k_mma_tf32(
    const float* __restrict__ A, const float* __restrict__ Bw,
    float* __restrict__ C, int lda, int ldb, int ldc)
{
    extern __shared__ float sm[];
    constexpr int ROWS = BM + BN;
    constexpr int STG = ROWS * 36;            // words per stage
    constexpr int MT = WM / 16, NT = WN / 8;
    constexpr int WARPS_N = BN / WN;
    constexpr int NCHUNK = ROWS * 8 / THREADS; // 16B chunks per thread per stage
    constexpr int NSTG = Dm / 32;              // 64

    const int tid = threadIdx.x;
    const int wid = tid >> 5, lane = tid & 31;
    const int g = lane >> 2, c = lane & 3;
    const int wm = (wid / WARPS_N) * WM, wn = (wid % WARPS_N) * WN;
    const int mBase = blockIdx.y * BM, nBase = blockIdx.x * BN;

    const uint32_t sbase = (uint32_t)__cvta_generic_to_shared(sm);

    float acc[MT][NT][4] = {};

    auto load_stage = [&](int s, int k0) {
        #pragma unroll
        for (int i = 0; i < NCHUNK; i++) {
            int idx = tid + i * THREADS;
            int row = idx >> 3, ch = idx & 7;
            const float* gptr = (row < BM)
                ? &A[(size_t)(mBase + row) * lda + k0 + ch * 4]
                : &Bw[(size_t)(nBase + row - BM) * ldb + k0 + ch * 4];
            cp16(sbase + (uint32_t)(s * STG + row * 36) * 4 + ch * 16, gptr);
        }
    };

    // prologue: STAGES-1 stages in flight
    #pragma unroll
    for (int s = 0; s < STAGES - 1; s++) { load_stage(s, s * 32); CP_COMMIT(); }

    for (int s = 0; s < NSTG; s++) {
        CP_WAIT(STAGES - 2);     // stage s landed
        __syncthreads();         // + all warps done with stage s-1

        const int nxt = s + STAGES - 1;
        if (nxt < NSTG) load_stage(nxt % STAGES, nxt * 32);
        CP_COMMIT();             // empty commits in tail keep accounting uniform

        const float* Ab = sm + (s % STAGES) * STG;
        const float* Bb = Ab + BM * 36;

        #pragma unroll
        for (int step = 0; step < 4; step++) {
            const int kk = step * 8;
            uint32_t af[MT][4], bf[NT][2];
            #pragma unroll
            for (int mt = 0; mt < MT; mt++) {
                int m0 = wm + mt * 16 + g;
                af[mt][0] = f2tf32(Ab[m0 * 36 + kk + c]);
                af[mt][1] = f2tf32(Ab[(m0 + 8) * 36 + kk + c]);
                af[mt][2] = f2tf32(Ab[m0 * 36 + kk + c + 4]);
                af[mt][3] = f2tf32(Ab[(m0 + 8) * 36 + kk + c + 4]);
            }
            #pragma unroll
            for (int nt = 0; nt < NT; nt++) {
                int n0 = wn + nt * 8 + g;
                bf[nt][0] = f2tf32(Bb[n0 * 36 + kk + c]);
                bf[nt][1] = f2tf32(Bb[n0 * 36 + kk + c + 4]);
            }
            #pragma unroll
            for (int mt = 0; mt < MT; mt++)
                #pragma unroll
                for (int nt = 0; nt < NT; nt++)
                    mma8(acc[mt][nt], af[mt], bf[nt]);
        }
    }

    // epilogue
    #pragma unroll
    for (int mt = 0; mt < MT; mt++) {
        const int row = mBase + wm + mt * 16 + g;
        #pragma unroll
        for (int nt = 0; nt < NT; nt++) {
            const int col = nBase + wn + nt * 8 + 2 * c;
            *reinterpret_cast<float2*>(&C[(size_t)row * ldc + col]) =
                make_float2(acc[mt][nt][0], acc[mt][nt][1]);
            *reinterpret_cast<float2*>(&C[(size_t)(row + 8) * ldc + col]) =
                make_float2(acc[mt][nt][2], acc[mt][nt][3]);
        }
    }
}

// ---------------------------------------------------------------------------
// Elementwise: gates + cache roll/scatter + depthwise conv + C-gate
// ---------------------------------------------------------------------------
__global__ __launch_bounds__(256) void k_elem(
    const float* __restrict__ conv_cache, const float* __restrict__ conv_w,
    const int* __restrict__ pos_ids, float* __restrict__ out_state)
{
    const int idx = blockIdx.x * 256 + threadIdx.x;   // b*2048 + d
    const int b = idx >> 11, d = idx & 2047;

    const float Bg = g_bcx[(size_t)b * 6144 + d];
    const float Cg = g_bcx[(size_t)b * 6144 + 2048 + d];
    const float xg = g_bcx[(size_t)b * 6144 + 4096 + d];
    const float Bx = Bg * xg;

    int pos = pos_ids[0];
    pos = min(max(pos, 0), 3);

    const float4 cc = *reinterpret_cast<const float4*>(conv_cache + (size_t)idx * 4);
    float st[4] = {cc.y, cc.z, cc.w, cc.x};   // roll left by 1
    st[pos] = Bx;

    const float4 cw = *reinterpret_cast<const float4*>(conv_w + (size_t)d * 4);
    const float co = st[0] * cw.x + st[1] * cw.y + st[2] * cw.z + st[3] * cw.w;

    g_y[idx] = Cg * co;
    *reinterpret_cast<float4*>(out_state + (size_t)idx * 4) =
        make_float4(st[0], st[1], st[2], st[3]);
}

// ---------------------------------------------------------------------------
extern "C" void kernel_launch(void* const* d_in, const int* in_sizes, int n_in,
                              void* d_out, int out_size) {
    const float* x          = (const float*)d_in[0];
    const float* conv_cache = (const float*)d_in[1];
    const float* w1         = (const float*)d_in[2];
    const float* w2         = (const float*)d_in[3];
    const float* conv_w     = (const float*)d_in[4];
    const int*   pos_ids    = (const int*)d_in[5];

    float* out       = (float*)d_out;            // [B,1,D]
    float* out_state = out + (size_t)Bm * Dm;    // [B,D,K]

    float* bcx = nullptr, *y = nullptr;
    cudaGetSymbolAddress((void**)&bcx, g_bcx);
    cudaGetSymbolAddress((void**)&y, g_y);

    // GEMM1: 64x128 tiles, 8 warps (32x32), 3 stages: smem = 3*192*36*4 = 82944 B
    constexpr int SMEM1 = 3 * (64 + 128) * 36 * 4;
    // GEMM2: 64x64 tiles, 8 warps (32x16), 3 stages: smem = 3*128*36*4 = 55296 B
    constexpr int SMEM2 = 3 * (64 + 64) * 36 * 4;
    cudaFuncSetAttribute((const void*)k_mma_tf32<64, 128, 32, 32, 256, 3>,
                         cudaFuncAttributeMaxDynamicSharedMemorySize, SMEM1);
    cudaFuncSetAttribute((const void*)k_mma_tf32<64, 64, 32, 16, 256, 3>,
                         cudaFuncAttributeMaxDynamicSharedMemorySize, SMEM2);

    // GEMM1: BCx[256, 6144] = x[256,2048] @ w1[6144,2048]^T   (192 CTAs)
    k_mma_tf32<64, 128, 32, 32, 256, 3><<<dim3(3 * Dm / 128, Bm / 64), 256, SMEM1>>>(
        x, w1, bcx, Dm, Dm, 3 * Dm);

    // gating + conv + state scatter
    k_elem<<<(Bm * Dm) / 256, 256>>>(conv_cache, conv_w, pos_ids, out_state);

    // GEMM2: out[256, 2048] = y[256,2048] @ w2[2048,2048]^T   (128 CTAs)
    k_mma_tf32<64, 64, 32, 16, 256, 3><<<dim3(Dm / 64, Bm / 64), 256, SMEM2>>>(
        y, w2, out, Dm, Dm, Dm);
}

// round 6
// speedup vs baseline: 4.0293x; 1.3534x over previous
#include <cuda_runtime.h>
#include <cstdint>

#define Dm 2048
#define Bm 256

// scratch (no cudaMalloc allowed)
__device__ float g_bcx[Bm * 3 * Dm];   // GEMM1 output [256, 6144]
__device__ float g_y[Bm * Dm];         // gated intermediate [256, 2048]

// pack two fp32 -> f16x2 (lo = a, hi = b)
__device__ __forceinline__ uint32_t pack_h2(float lo, float hi) {
    uint32_t r;
    asm("cvt.rn.f16x2.f32 %0, %1, %2;" : "=r"(r) : "f"(hi), "f"(lo));
    return r;
}

__device__ __forceinline__ void mma16(float* d, const uint32_t* a, const uint32_t* b) {
    asm volatile(
        "mma.sync.aligned.m16n8k16.row.col.f32.f16.f16.f32 "
        "{%0,%1,%2,%3}, {%4,%5,%6,%7}, {%8,%9}, {%0,%1,%2,%3};"
        : "+f"(d[0]), "+f"(d[1]), "+f"(d[2]), "+f"(d[3])
        : "r"(a[0]), "r"(a[1]), "r"(a[2]), "r"(a[3]), "r"(b[0]), "r"(b[1]));
}

__device__ __forceinline__ void ldsm4(uint32_t* r, uint32_t addr) {
    asm volatile("ldmatrix.sync.aligned.m8n8.x4.shared.b16 {%0,%1,%2,%3}, [%4];"
                 : "=r"(r[0]), "=r"(r[1]), "=r"(r[2]), "=r"(r[3]) : "r"(addr));
}
__device__ __forceinline__ uint32_t lds32(uint32_t addr) {
    uint32_t v; asm volatile("ld.shared.b32 %0, [%1];" : "=r"(v) : "r"(addr));
    return v;
}
__device__ __forceinline__ void sts64(uint32_t addr, uint32_t u0, uint32_t u1) {
    asm volatile("st.shared.v2.b32 [%0], {%1,%2};" :: "r"(addr), "r"(u0), "r"(u1));
}

// ---------------------------------------------------------------------------
// fp16 tensor-core GEMM: C[M,N] = A[M,K] @ Bw[N,K]^T  (fp32 in/out, f16 MMA)
// Smem rows: 32 K-halves padded to 40 (80B pitch) -> conflict-free ldmatrix.
// Reg-staged LDG prefetch, fp32->f16x2 pack at STS, 2 smem buffers, 1 sync.
// ---------------------------------------------------------------------------
template <int BM, int BN, int WM, int WN, int THREADS>
__global__ __launch_bounds__(THREADS, 2) void k_mma_f16(
    const float* __restrict__ A, const float* __restrict__ Bw,
    float* __restrict__ C, int lda, int ldb, int ldc)
{
    extern __shared__ uint8_t smem[];
    constexpr int ROWS = BM + BN;
    constexpr int STGB = ROWS * 80;            // bytes per stage (40 halves/row)
    constexpr int MT = WM / 16, NT = WN / 8;
    constexpr int WARPS_N = BN / WN;
    constexpr int NCHUNK = ROWS * 32 / (4 * THREADS); // float4 per thread/stage
    constexpr int NSTG = Dm / 32;              // 64

    const int tid = threadIdx.x;
    const int wid = tid >> 5, lane = tid & 31;
    const int g = lane >> 2, c = lane & 3;
    const int wm = (wid / WARPS_N) * WM, wn = (wid % WARPS_N) * WN;
    const int mBase = blockIdx.y * BM, nBase = blockIdx.x * BN;

    const uint32_t sbase = (uint32_t)__cvta_generic_to_shared(smem);

    // precomputed per-thread smem offsets
    const int lr = lane & 7, mat = lane >> 3;
    uint32_t aoff[MT];
    #pragma unroll
    for (int mt = 0; mt < MT; mt++)
        aoff[mt] = (uint32_t)(wm + mt * 16 + lr + (mat & 1) * 8) * 80
                 + (uint32_t)(mat >> 1) * 16;
    uint32_t boff[NT];
    #pragma unroll
    for (int nt = 0; nt < NT; nt++)
        boff[nt] = (uint32_t)(BM + wn + nt * 8 + g) * 80 + c * 4;

    float acc[MT][NT][4] = {};
    float4 ra[NCHUNK];

    auto ldg = [&](int k0) {
        #pragma unroll
        for (int i = 0; i < NCHUNK; i++) {
            int idx = tid + i * THREADS;
            int row = idx >> 3, ch = idx & 7;
            const float* gptr = (row < BM)
                ? &A[(size_t)(mBase + row) * lda + k0 + ch * 4]
                : &Bw[(size_t)(nBase + row - BM) * ldb + k0 + ch * 4];
            ra[i] = *reinterpret_cast<const float4*>(gptr);
        }
    };
    auto sts = [&](int buf) {
        #pragma unroll
        for (int i = 0; i < NCHUNK; i++) {
            int idx = tid + i * THREADS;
            int row = idx >> 3, ch = idx & 7;
            sts64(sbase + buf * STGB + (uint32_t)row * 80 + ch * 8,
                  pack_h2(ra[i].x, ra[i].y), pack_h2(ra[i].z, ra[i].w));
        }
    };

    ldg(0);

    for (int s = 0; s < NSTG; s++) {
        const int buf = s & 1;
        sts(buf);
        __syncthreads();
        if (s + 1 < NSTG) ldg((s + 1) * 32);

        const uint32_t sb = sbase + buf * STGB;
        #pragma unroll
        for (int step = 0; step < 2; step++) {      // two k16 steps per stage
            const uint32_t kb = step * 32;          // 16 halves = 32 bytes
            uint32_t af[MT][4], bf[NT][2];
            #pragma unroll
            for (int mt = 0; mt < MT; mt++)
                ldsm4(af[mt], sb + aoff[mt] + kb);
            #pragma unroll
            for (int nt = 0; nt < NT; nt++) {
                bf[nt][0] = lds32(sb + boff[nt] + kb);
                bf[nt][1] = lds32(sb + boff[nt] + kb + 16);
            }
            #pragma unroll
            for (int mt = 0; mt < MT; mt++)
                #pragma unroll
                for (int nt = 0; nt < NT; nt++)
                    mma16(acc[mt][nt], af[mt], bf[nt]);
        }
    }

    // epilogue: c0,c1 -> (row g, 2c), c2,c3 -> (row g+8, 2c)
    #pragma unroll
    for (int mt = 0; mt < MT; mt++) {
        const int row = mBase + wm + mt * 16 + g;
        #pragma unroll
        for (int nt = 0; nt < NT; nt++) {
            const int col = nBase + wn + nt * 8 + 2 * c;
            *reinterpret_cast<float2*>(&C[(size_t)row * ldc + col]) =
                make_float2(acc[mt][nt][0], acc[mt][nt][1]);
            *reinterpret_cast<float2*>(&C[(size_t)(row + 8) * ldc + col]) =
                make_float2(acc[mt][nt][2], acc[mt][nt][3]);
        }
    }
}

// ---------------------------------------------------------------------------
// Elementwise: gates + cache roll/scatter + depthwise conv + C-gate
// ---------------------------------------------------------------------------
__global__ __launch_bounds__(256) void k_elem(
    const float* __restrict__ conv_cache, const float* __restrict__ conv_w,
    const int* __restrict__ pos_ids, float* __restrict__ out_state)
{
    const int idx = blockIdx.x * 256 + threadIdx.x;   // b*2048 + d
    const int b = idx >> 11, d = idx & 2047;

    const float Bg = g_bcx[(size_t)b * 6144 + d];
    const float Cg = g_bcx[(size_t)b * 6144 + 2048 + d];
    const float xg = g_bcx[(size_t)b * 6144 + 4096 + d];
    const float Bx = Bg * xg;

    int pos = pos_ids[0];
    pos = min(max(pos, 0), 3);

    const float4 cc = *reinterpret_cast<const float4*>(conv_cache + (size_t)idx * 4);
    float st[4] = {cc.y, cc.z, cc.w, cc.x};   // roll left by 1
    st[pos] = Bx;

    const float4 cw = *reinterpret_cast<const float4*>(conv_w + (size_t)d * 4);
    const float co = st[0] * cw.x + st[1] * cw.y + st[2] * cw.z + st[3] * cw.w;

    g_y[idx] = Cg * co;
    *reinterpret_cast<float4*>(out_state + (size_t)idx * 4) =
        make_float4(st[0], st[1], st[2], st[3]);
}

// ---------------------------------------------------------------------------
extern "C" void kernel_launch(void* const* d_in, const int* in_sizes, int n_in,
                              void* d_out, int out_size) {
    const float* x          = (const float*)d_in[0];
    const float* conv_cache = (const float*)d_in[1];
    const float* w1         = (const float*)d_in[2];
    const float* w2         = (const float*)d_in[3];
    const float* conv_w     = (const float*)d_in[4];
    const int*   pos_ids    = (const int*)d_in[5];

    float* out       = (float*)d_out;            // [B,1,D]
    float* out_state = out + (size_t)Bm * Dm;    // [B,D,K]

    float* bcx = nullptr, *y = nullptr;
    cudaGetSymbolAddress((void**)&bcx, g_bcx);
    cudaGetSymbolAddress((void**)&y, g_y);

    // GEMM1: 64x128, 8 warps (32x32), smem = 2*192*80 = 30720 B, 192 CTAs
    constexpr int SMEM1 = 2 * (64 + 128) * 80;
    // GEMM2: 64x64, 8 warps (32x16), smem = 2*128*80 = 20480 B, 128 CTAs
    constexpr int SMEM2 = 2 * (64 + 64) * 80;
    cudaFuncSetAttribute((const void*)k_mma_f16<64, 128, 32, 32, 256>,
                         cudaFuncAttributeMaxDynamicSharedMemorySize, SMEM1);
    cudaFuncSetAttribute((const void*)k_mma_f16<64, 64, 32, 16, 256>,
                         cudaFuncAttributeMaxDynamicSharedMemorySize, SMEM2);

    // GEMM1: BCx[256, 6144] = x[256,2048] @ w1[6144,2048]^T
    k_mma_f16<64, 128, 32, 32, 256><<<dim3(3 * Dm / 128, Bm / 64), 256, SMEM1>>>(
        x, w1, bcx, Dm, Dm, 3 * Dm);

    // gating + conv + state scatter
    k_elem<<<(Bm * Dm) / 256, 256>>>(conv_cache, conv_w, pos_ids, out_state);

    // GEMM2: out[256, 2048] = y[256,2048] @ w2[2048,2048]^T
    k_mma_f16<64, 64, 32, 16, 256><<<dim3(Dm / 64, Bm / 64), 256, SMEM2>>>(
        y, w2, out, Dm, Dm, Dm);
}

// round 7
// speedup vs baseline: 4.2090x; 1.0446x over previous
#include <cuda_runtime.h>
#include <cuda_fp16.h>
#include <cstdint>

#define Dm 2048
#define Bm 256

// scratch (no cudaMalloc allowed)
__device__ float g_bcx[Bm * 3 * Dm];                 // GEMM1 out [256, 6144] fp32
__device__ __align__(16) __half g_w1h[3 * Dm * Dm];  // w1 fp16 [6144, 2048]
__device__ __align__(16) __half g_w2h[Dm * Dm];      // w2 fp16 [2048, 2048]
__device__ __align__(16) __half g_xh[Bm * Dm];       // x  fp16 [256, 2048]
__device__ __align__(16) __half g_yh[Bm * Dm];       // y  fp16 [256, 2048]

// pack two fp32 -> f16x2 (lo = first arg -> low half / lower address)
__device__ __forceinline__ uint32_t pack_h2(float lo, float hi) {
    uint32_t r;
    asm("cvt.rn.f16x2.f32 %0, %1, %2;" : "=r"(r) : "f"(hi), "f"(lo));
    return r;
}

__device__ __forceinline__ void mma16(float* d, const uint32_t* a, const uint32_t* b) {
    asm volatile(
        "mma.sync.aligned.m16n8k16.row.col.f32.f16.f16.f32 "
        "{%0,%1,%2,%3}, {%4,%5,%6,%7}, {%8,%9}, {%0,%1,%2,%3};"
        : "+f"(d[0]), "+f"(d[1]), "+f"(d[2]), "+f"(d[3])
        : "r"(a[0]), "r"(a[1]), "r"(a[2]), "r"(a[3]), "r"(b[0]), "r"(b[1]));
}

__device__ __forceinline__ void ldsm4(uint32_t* r, uint32_t addr) {
    asm volatile("ldmatrix.sync.aligned.m8n8.x4.shared.b16 {%0,%1,%2,%3}, [%4];"
                 : "=r"(r[0]), "=r"(r[1]), "=r"(r[2]), "=r"(r[3]) : "r"(addr));
}
__device__ __forceinline__ uint32_t lds32(uint32_t addr) {
    uint32_t v; asm volatile("ld.shared.b32 %0, [%1];" : "=r"(v) : "r"(addr));
    return v;
}
__device__ __forceinline__ void cp16(uint32_t saddr, const void* gptr) {
    asm volatile("cp.async.cg.shared.global [%0], [%1], 16;"
                 :: "r"(saddr), "l"(gptr));
}
#define CP_COMMIT() asm volatile("cp.async.commit_group;" ::: "memory")
#define CP_WAIT(n)  asm volatile("cp.async.wait_group %0;" :: "n"(n) : "memory")

// ---------------------------------------------------------------------------
// fp32 -> fp16 convert (vectorized, HBM-bound)
// ---------------------------------------------------------------------------
__global__ __launch_bounds__(256) void k_cvt(
    const float4* __restrict__ src, uint2* __restrict__ dst, int n4)
{
    int i = blockIdx.x * 256 + threadIdx.x;
    if (i < n4) {
        float4 v = src[i];
        dst[i] = make_uint2(pack_h2(v.x, v.y), pack_h2(v.z, v.w));
    }
}

// ---------------------------------------------------------------------------
// fp16 tensor-core GEMM, cp.async multi-stage: C[M,N] = A[M,K] @ Bw[N,K]^T
// Smem rows: 32 K-halves (64B) padded to 80B pitch -> conflict-free ldmatrix
// + B-frag LDS. STAGES-deep cp.async pipeline, no register staging.
// ---------------------------------------------------------------------------
template <int BM, int BN, int WM, int WN, int THREADS, int STAGES>
__global__ __launch_bounds__(THREADS, 2) void k_mma_f16cp(
    const __half* __restrict__ A, const __half* __restrict__ Bw,
    float* __restrict__ C, int lda, int ldb, int ldc)
{
    extern __shared__ uint8_t smem[];
    constexpr int ROWS = BM + BN;
    constexpr int STGB = ROWS * 80;            // bytes per stage
    constexpr int MT = WM / 16, NT = WN / 8;
    constexpr int WARPS_N = BN / WN;
    constexpr int NCHUNK = ROWS * 4 / THREADS; // 16B chunks per thread/stage
    constexpr int NSTG = Dm / 32;              // 64

    const int tid = threadIdx.x;
    const int wid = tid >> 5, lane = tid & 31;
    const int g = lane >> 2, c = lane & 3;
    const int wm = (wid / WARPS_N) * WM, wn = (wid % WARPS_N) * WN;
    const int mBase = blockIdx.y * BM, nBase = blockIdx.x * BN;

    const uint32_t sbase = (uint32_t)__cvta_generic_to_shared(smem);

    // per-thread fragment smem offsets (pitch 80B: banks 20r+c -> conflict-free)
    const int lr = lane & 7, mat = lane >> 3;
    uint32_t aoff[MT];
    #pragma unroll
    for (int mt = 0; mt < MT; mt++)
        aoff[mt] = (uint32_t)(wm + mt * 16 + lr + (mat & 1) * 8) * 80
                 + (uint32_t)(mat >> 1) * 16;
    uint32_t boff[NT];
    #pragma unroll
    for (int nt = 0; nt < NT; nt++)
        boff[nt] = (uint32_t)(BM + wn + nt * 8 + g) * 80 + c * 4;

    float acc[MT][NT][4] = {};

    auto load_stage = [&](int s, int k0) {   // k0 in halves
        #pragma unroll
        for (int i = 0; i < NCHUNK; i++) {
            int idx = tid + i * THREADS;
            int row = idx >> 2, ch = idx & 3;
            const __half* gptr = (row < BM)
                ? &A[(size_t)(mBase + row) * lda + k0 + ch * 8]
                : &Bw[(size_t)(nBase + row - BM) * ldb + k0 + ch * 8];
            cp16(sbase + s * STGB + (uint32_t)row * 80 + ch * 16, gptr);
        }
    };

    // prologue: STAGES-1 stages in flight
    #pragma unroll
    for (int s = 0; s < STAGES - 1; s++) { load_stage(s, s * 32); CP_COMMIT(); }

    for (int s = 0; s < NSTG; s++) {
        CP_WAIT(STAGES - 2);     // stage s landed
        __syncthreads();         // all warps done with stage s-1 (its buffer reused)

        const int nxt = s + STAGES - 1;
        if (nxt < NSTG) load_stage(nxt % STAGES, nxt * 32);
        CP_COMMIT();             // empty commits in tail keep group accounting

        const uint32_t sb = sbase + (s % STAGES) * STGB;
        #pragma unroll
        for (int step = 0; step < 2; step++) {      // two k16 steps per stage
            const uint32_t kb = step * 32;          // 16 halves = 32 bytes
            uint32_t af[MT][4], bf[NT][2];
            #pragma unroll
            for (int mt = 0; mt < MT; mt++)
                ldsm4(af[mt], sb + aoff[mt] + kb);
            #pragma unroll
            for (int nt = 0; nt < NT; nt++) {
                bf[nt][0] = lds32(sb + boff[nt] + kb);
                bf[nt][1] = lds32(sb + boff[nt] + kb + 16);
            }
            #pragma unroll
            for (int mt = 0; mt < MT; mt++)
                #pragma unroll
                for (int nt = 0; nt < NT; nt++)
                    mma16(acc[mt][nt], af[mt], bf[nt]);
        }
    }

    // epilogue: c0,c1 -> (row g, 2c), c2,c3 -> (row g+8, 2c)
    #pragma unroll
    for (int mt = 0; mt < MT; mt++) {
        const int row = mBase + wm + mt * 16 + g;
        #pragma unroll
        for (int nt = 0; nt < NT; nt++) {
            const int col = nBase + wn + nt * 8 + 2 * c;
            *reinterpret_cast<float2*>(&C[(size_t)row * ldc + col]) =
                make_float2(acc[mt][nt][0], acc[mt][nt][1]);
            *reinterpret_cast<float2*>(&C[(size_t)(row + 8) * ldc + col]) =
                make_float2(acc[mt][nt][2], acc[mt][nt][3]);
        }
    }
}

// ---------------------------------------------------------------------------
// Elementwise: gates + cache roll/scatter + depthwise conv + C-gate.
// Emits y directly as fp16 for GEMM2.
// ---------------------------------------------------------------------------
__global__ __launch_bounds__(256) void k_elem(
    const float* __restrict__ conv_cache, const float* __restrict__ conv_w,
    const int* __restrict__ pos_ids, float* __restrict__ out_state)
{
    const int idx = blockIdx.x * 256 + threadIdx.x;   // b*2048 + d
    const int b = idx >> 11, d = idx & 2047;

    const float Bg = g_bcx[(size_t)b * 6144 + d];
    const float Cg = g_bcx[(size_t)b * 6144 + 2048 + d];
    const float xg = g_bcx[(size_t)b * 6144 + 4096 + d];
    const float Bx = Bg * xg;

    int pos = pos_ids[0];
    pos = min(max(pos, 0), 3);

    const float4 cc = *reinterpret_cast<const float4*>(conv_cache + (size_t)idx * 4);
    float st[4] = {cc.y, cc.z, cc.w, cc.x};   // roll left by 1
    st[pos] = Bx;

    const float4 cw = *reinterpret_cast<const float4*>(conv_w + (size_t)d * 4);
    const float co = st[0] * cw.x + st[1] * cw.y + st[2] * cw.z + st[3] * cw.w;

    g_yh[idx] = __float2half(Cg * co);
    *reinterpret_cast<float4*>(out_state + (size_t)idx * 4) =
        make_float4(st[0], st[1], st[2], st[3]);
}

// ---------------------------------------------------------------------------
extern "C" void kernel_launch(void* const* d_in, const int* in_sizes, int n_in,
                              void* d_out, int out_size) {
    const float* x          = (const float*)d_in[0];
    const float* conv_cache = (const float*)d_in[1];
    const float* w1         = (const float*)d_in[2];
    const float* w2         = (const float*)d_in[3];
    const float* conv_w     = (const float*)d_in[4];
    const int*   pos_ids    = (const int*)d_in[5];

    float* out       = (float*)d_out;            // [B,1,D]
    float* out_state = out + (size_t)Bm * Dm;    // [B,D,K]

    float* bcx = nullptr;
    __half *w1h = nullptr, *w2h = nullptr, *xh = nullptr, *yh = nullptr;
    cudaGetSymbolAddress((void**)&bcx, g_bcx);
    cudaGetSymbolAddress((void**)&w1h, g_w1h);
    cudaGetSymbolAddress((void**)&w2h, g_w2h);
    cudaGetSymbolAddress((void**)&xh, g_xh);
    cudaGetSymbolAddress((void**)&yh, g_yh);

    // fp32 -> fp16 converts (HBM-bound)
    k_cvt<<<(3 * Dm * Dm / 4) / 256, 256>>>((const float4*)w1, (uint2*)w1h,
                                            3 * Dm * Dm / 4);
    k_cvt<<<(Dm * Dm / 4) / 256, 256>>>((const float4*)w2, (uint2*)w2h,
                                        Dm * Dm / 4);
    k_cvt<<<(Bm * Dm / 4) / 256, 256>>>((const float4*)x, (uint2*)xh,
                                        Bm * Dm / 4);

    // GEMM1: 64x128, 8 warps (32x32), 5 stages: smem = 5*192*80 = 76800 B
    constexpr int SMEM1 = 5 * (64 + 128) * 80;
    // GEMM2: 64x64, 8 warps (32x16), 5 stages: smem = 5*128*80 = 51200 B
    constexpr int SMEM2 = 5 * (64 + 64) * 80;
    cudaFuncSetAttribute((const void*)k_mma_f16cp<64, 128, 32, 32, 256, 5>,
                         cudaFuncAttributeMaxDynamicSharedMemorySize, SMEM1);
    cudaFuncSetAttribute((const void*)k_mma_f16cp<64, 64, 32, 16, 256, 5>,
                         cudaFuncAttributeMaxDynamicSharedMemorySize, SMEM2);

    // GEMM1: BCx[256, 6144] = x[256,2048] @ w1[6144,2048]^T   (192 CTAs)
    k_mma_f16cp<64, 128, 32, 32, 256, 5><<<dim3(3 * Dm / 128, Bm / 64), 256, SMEM1>>>(
        xh, w1h, bcx, Dm, Dm, 3 * Dm);

    // gating + conv + state scatter
    k_elem<<<(Bm * Dm) / 256, 256>>>(conv_cache, conv_w, pos_ids, out_state);

    // GEMM2: out[256, 2048] = y[256,2048] @ w2[2048,2048]^T   (128 CTAs)
    k_mma_f16cp<64, 64, 32, 16, 256, 5><<<dim3(Dm / 64, Bm / 64), 256, SMEM2>>>(
        yh, w2h, out, Dm, Dm, Dm);
}

// round 8
// speedup vs baseline: 5.1803x; 1.2308x over previous
#include <cuda_runtime.h>
#include <cuda_fp16.h>
#include <cstdint>

#define Dm 2048
#define Bm 256

// scratch (no cudaMalloc allowed)
__device__ float g_bcx[Bm * 3 * Dm];                 // GEMM1 out [256, 6144] fp32
__device__ __align__(16) __half g_w1h[3 * Dm * Dm];  // w1 fp16 [6144, 2048]
__device__ __align__(16) __half g_w2h[Dm * Dm];      // w2 fp16 [2048, 2048]
__device__ __align__(16) __half g_xh[Bm * Dm];       // x  fp16 [256, 2048]
__device__ __align__(16) __half g_yh[Bm * Dm];       // y  fp16 [256, 2048]

__device__ __forceinline__ uint32_t pack_h2(float lo, float hi) {
    uint32_t r;
    asm("cvt.rn.f16x2.f32 %0, %1, %2;" : "=r"(r) : "f"(hi), "f"(lo));
    return r;
}

__device__ __forceinline__ void mma16(float* d, const uint32_t* a, const uint32_t* b) {
    asm volatile(
        "mma.sync.aligned.m16n8k16.row.col.f32.f16.f16.f32 "
        "{%0,%1,%2,%3}, {%4,%5,%6,%7}, {%8,%9}, {%0,%1,%2,%3};"
        : "+f"(d[0]), "+f"(d[1]), "+f"(d[2]), "+f"(d[3])
        : "r"(a[0]), "r"(a[1]), "r"(a[2]), "r"(a[3]), "r"(b[0]), "r"(b[1]));
}

__device__ __forceinline__ void ldsm4(uint32_t* r, uint32_t addr) {
    asm volatile("ldmatrix.sync.aligned.m8n8.x4.shared.b16 {%0,%1,%2,%3}, [%4];"
                 : "=r"(r[0]), "=r"(r[1]), "=r"(r[2]), "=r"(r[3]) : "r"(addr));
}
__device__ __forceinline__ uint32_t lds32(uint32_t addr) {
    uint32_t v; asm volatile("ld.shared.b32 %0, [%1];" : "=r"(v) : "r"(addr));
    return v;
}
__device__ __forceinline__ void cp16(uint32_t saddr, const void* gptr) {
    asm volatile("cp.async.cg.shared.global [%0], [%1], 16;"
                 :: "r"(saddr), "l"(gptr));
}
#define CP_COMMIT() asm volatile("cp.async.commit_group;" ::: "memory")
#define CP_WAIT(n)  asm volatile("cp.async.wait_group %0;" :: "n"(n) : "memory")

// ---------------------------------------------------------------------------
// fp32 -> fp16 convert (vectorized, HBM-bound)
// ---------------------------------------------------------------------------
__global__ __launch_bounds__(256) void k_cvt(
    const float4* __restrict__ src, uint2* __restrict__ dst, int n4)
{
    int i = blockIdx.x * 256 + threadIdx.x;
    if (i < n4) {
        float4 v = src[i];
        dst[i] = make_uint2(pack_h2(v.x, v.y), pack_h2(v.z, v.w));
    }
}

// ---------------------------------------------------------------------------
// fp16 tensor-core GEMM, cp.async multi-stage: C[M,N] = A[M,K] @ Bw[N,K]^T
// BK halves per stage (BK*2 bytes/row, padded +16B pitch -> conflict-free
// ldmatrix & B-frag LDS). Single-wave grids; no register staging.
// ---------------------------------------------------------------------------
template <int BM, int BN, int BK, int WM, int WN, int THREADS, int STAGES>
__global__ __launch_bounds__(THREADS, 1) void k_mma_f16cp(
    const __half* __restrict__ A, const __half* __restrict__ Bw,
    float* __restrict__ C, int lda, int ldb, int ldc)
{
    extern __shared__ uint8_t smem[];
    constexpr int ROWS = BM + BN;
    constexpr int PITCH = BK * 2 + 16;         // bytes per smem row
    constexpr int STGB = ROWS * PITCH;
    constexpr int MT = WM / 16, NT = WN / 8;
    constexpr int WARPS_N = BN / WN;
    constexpr int RCH = BK * 2 / 16;           // 16B chunks per row
    constexpr int NCHUNK = ROWS * RCH / THREADS;
    constexpr int NSTG = Dm / BK;
    constexpr int KSTEPS = BK / 16;

    const int tid = threadIdx.x;
    const int wid = tid >> 5, lane = tid & 31;
    const int g = lane >> 2, c = lane & 3;
    const int wm = (wid / WARPS_N) * WM, wn = (wid % WARPS_N) * WN;
    const int mBase = blockIdx.y * BM, nBase = blockIdx.x * BN;

    const uint32_t sbase = (uint32_t)__cvta_generic_to_shared(smem);

    const int lr = lane & 7, mat = lane >> 3;
    uint32_t aoff[MT];
    #pragma unroll
    for (int mt = 0; mt < MT; mt++)
        aoff[mt] = (uint32_t)(wm + mt * 16 + lr + (mat & 1) * 8) * PITCH
                 + (uint32_t)(mat >> 1) * 16;
    uint32_t boff[NT];
    #pragma unroll
    for (int nt = 0; nt < NT; nt++)
        boff[nt] = (uint32_t)(BM + wn + nt * 8 + g) * PITCH + c * 4;

    float acc[MT][NT][4] = {};

    auto load_stage = [&](int s, int k0) {   // k0 in halves
        #pragma unroll
        for (int i = 0; i < NCHUNK; i++) {
            int idx = tid + i * THREADS;
            int row = idx / RCH, ch = idx % RCH;
            const __half* gptr = (row < BM)
                ? &A[(size_t)(mBase + row) * lda + k0 + ch * 8]
                : &Bw[(size_t)(nBase + row - BM) * ldb + k0 + ch * 8];
            cp16(sbase + s * STGB + (uint32_t)row * PITCH + ch * 16, gptr);
        }
    };

    #pragma unroll
    for (int s = 0; s < STAGES - 1; s++) { load_stage(s, s * BK); CP_COMMIT(); }

    for (int s = 0; s < NSTG; s++) {
        CP_WAIT(STAGES - 2);
        __syncthreads();

        const int nxt = s + STAGES - 1;
        if (nxt < NSTG) load_stage(nxt % STAGES, nxt * BK);
        CP_COMMIT();

        const uint32_t sb = sbase + (s % STAGES) * STGB;
        #pragma unroll
        for (int step = 0; step < KSTEPS; step++) {
            const uint32_t kb = step * 32;          // 16 halves = 32 bytes
            uint32_t af[MT][4], bf[NT][2];
            #pragma unroll
            for (int mt = 0; mt < MT; mt++)
                ldsm4(af[mt], sb + aoff[mt] + kb);
            #pragma unroll
            for (int nt = 0; nt < NT; nt++) {
                bf[nt][0] = lds32(sb + boff[nt] + kb);
                bf[nt][1] = lds32(sb + boff[nt] + kb + 16);
            }
            #pragma unroll
            for (int mt = 0; mt < MT; mt++)
                #pragma unroll
                for (int nt = 0; nt < NT; nt++)
                    mma16(acc[mt][nt], af[mt], bf[nt]);
        }
    }

    #pragma unroll
    for (int mt = 0; mt < MT; mt++) {
        const int row = mBase + wm + mt * 16 + g;
        #pragma unroll
        for (int nt = 0; nt < NT; nt++) {
            const int col = nBase + wn + nt * 8 + 2 * c;
            *reinterpret_cast<float2*>(&C[(size_t)row * ldc + col]) =
                make_float2(acc[mt][nt][0], acc[mt][nt][1]);
            *reinterpret_cast<float2*>(&C[(size_t)(row + 8) * ldc + col]) =
                make_float2(acc[mt][nt][2], acc[mt][nt][3]);
        }
    }
}

// ---------------------------------------------------------------------------
// Elementwise: gates + cache roll/scatter + depthwise conv + C-gate.
// Emits y directly as fp16 for GEMM2.
// ---------------------------------------------------------------------------
__global__ __launch_bounds__(256) void k_elem(
    const float* __restrict__ conv_cache, const float* __restrict__ conv_w,
    const int* __restrict__ pos_ids, float* __restrict__ out_state)
{
    const int idx = blockIdx.x * 256 + threadIdx.x;   // b*2048 + d
    const int b = idx >> 11, d = idx & 2047;

    const float Bg = g_bcx[(size_t)b * 6144 + d];
    const float Cg = g_bcx[(size_t)b * 6144 + 2048 + d];
    const float xg = g_bcx[(size_t)b * 6144 + 4096 + d];
    const float Bx = Bg * xg;

    int pos = pos_ids[0];
    pos = min(max(pos, 0), 3);

    const float4 cc = *reinterpret_cast<const float4*>(conv_cache + (size_t)idx * 4);
    float st[4] = {cc.y, cc.z, cc.w, cc.x};   // roll left by 1
    st[pos] = Bx;

    const float4 cw = *reinterpret_cast<const float4*>(conv_w + (size_t)d * 4);
    const float co = st[0] * cw.x + st[1] * cw.y + st[2] * cw.z + st[3] * cw.w;

    g_yh[idx] = __float2half(Cg * co);
    *reinterpret_cast<float4*>(out_state + (size_t)idx * 4) =
        make_float4(st[0], st[1], st[2], st[3]);
}

// ---------------------------------------------------------------------------
extern "C" void kernel_launch(void* const* d_in, const int* in_sizes, int n_in,
                              void* d_out, int out_size) {
    const float* x          = (const float*)d_in[0];
    const float* conv_cache = (const float*)d_in[1];
    const float* w1         = (const float*)d_in[2];
    const float* w2         = (const float*)d_in[3];
    const float* conv_w     = (const float*)d_in[4];
    const int*   pos_ids    = (const int*)d_in[5];

    float* out       = (float*)d_out;            // [B,1,D]
    float* out_state = out + (size_t)Bm * Dm;    // [B,D,K]

    float* bcx = nullptr;
    __half *w1h = nullptr, *w2h = nullptr, *xh = nullptr, *yh = nullptr;
    cudaGetSymbolAddress((void**)&bcx, g_bcx);
    cudaGetSymbolAddress((void**)&w1h, g_w1h);
    cudaGetSymbolAddress((void**)&w2h, g_w2h);
    cudaGetSymbolAddress((void**)&xh, g_xh);
    cudaGetSymbolAddress((void**)&yh, g_yh);

    // fp32 -> fp16 converts (HBM-bound)
    k_cvt<<<(3 * Dm * Dm / 4) / 256, 256>>>((const float4*)w1, (uint2*)w1h,
                                            3 * Dm * Dm / 4);
    k_cvt<<<(Dm * Dm / 4) / 256, 256>>>((const float4*)w2, (uint2*)w2h,
                                        Dm * Dm / 4);
    k_cvt<<<(Bm * Dm / 4) / 256, 256>>>((const float4*)x, (uint2*)xh,
                                        Bm * Dm / 4);

    // GEMM1: 128x96 tile, BK=64, 8 warps (32x48), 4 stages
    // smem = 4 * 224 * 144 = 129024 B; grid = 64 x 2 = 128 CTAs (one wave)
    constexpr int SMEM1 = 4 * (128 + 96) * 144;
    // GEMM2: 64x64 tile, BK=64, 8 warps (32x16), 4 stages
    // smem = 4 * 128 * 144 = 73728 B; grid = 32 x 4 = 128 CTAs (one wave)
    constexpr int SMEM2 = 4 * (64 + 64) * 144;
    cudaFuncSetAttribute((const void*)k_mma_f16cp<128, 96, 64, 32, 48, 256, 4>,
                         cudaFuncAttributeMaxDynamicSharedMemorySize, SMEM1);
    cudaFuncSetAttribute((const void*)k_mma_f16cp<64, 64, 64, 32, 16, 256, 4>,
                         cudaFuncAttributeMaxDynamicSharedMemorySize, SMEM2);

    // GEMM1: BCx[256, 6144] = x[256,2048] @ w1[6144,2048]^T
    k_mma_f16cp<128, 96, 64, 32, 48, 256, 4><<<dim3(3 * Dm / 96, Bm / 128), 256, SMEM1>>>(
        xh, w1h, bcx, Dm, Dm, 3 * Dm);

    // gating + conv + state scatter
    k_elem<<<(Bm * Dm) / 256, 256>>>(conv_cache, conv_w, pos_ids, out_state);

    // GEMM2: out[256, 2048] = y[256,2048] @ w2[2048,2048]^T
    k_mma_f16cp<64, 64, 64, 32, 16, 256, 4><<<dim3(Dm / 64, Bm / 64), 256, SMEM2>>>(
        yh, w2h, out, Dm, Dm, Dm);
}

// round 9
// speedup vs baseline: 5.7749x; 1.1148x over previous
#include <cuda_runtime.h>
#include <cuda_fp16.h>
#include <cstdint>

#define Dm 2048
#define Bm 256

// scratch (no cudaMalloc allowed)
__device__ float g_bcx[Bm * 3 * Dm];                 // GEMM1 out [256, 6144] fp32
__device__ __align__(16) __half g_w1h[3 * Dm * Dm];  // w1 fp16 [6144, 2048]
__device__ __align__(16) __half g_w2h[Dm * Dm];      // w2 fp16 [2048, 2048]
__device__ __align__(16) __half g_xh[Bm * Dm];       // x  fp16 [256, 2048]
__device__ __align__(16) __half g_yh[Bm * Dm];       // y  fp16 [256, 2048]

__device__ __forceinline__ uint32_t pack_h2(float lo, float hi) {
    uint32_t r;
    asm("cvt.rn.f16x2.f32 %0, %1, %2;" : "=r"(r) : "f"(hi), "f"(lo));
    return r;
}

__device__ __forceinline__ void mma16(float* d, const uint32_t* a, const uint32_t* b) {
    asm volatile(
        "mma.sync.aligned.m16n8k16.row.col.f32.f16.f16.f32 "
        "{%0,%1,%2,%3}, {%4,%5,%6,%7}, {%8,%9}, {%0,%1,%2,%3};"
        : "+f"(d[0]), "+f"(d[1]), "+f"(d[2]), "+f"(d[3])
        : "r"(a[0]), "r"(a[1]), "r"(a[2]), "r"(a[3]), "r"(b[0]), "r"(b[1]));
}

__device__ __forceinline__ void ldsm4(uint32_t* r, uint32_t addr) {
    asm volatile("ldmatrix.sync.aligned.m8n8.x4.shared.b16 {%0,%1,%2,%3}, [%4];"
                 : "=r"(r[0]), "=r"(r[1]), "=r"(r[2]), "=r"(r[3]) : "r"(addr));
}
__device__ __forceinline__ uint32_t lds32(uint32_t addr) {
    uint32_t v; asm volatile("ld.shared.b32 %0, [%1];" : "=r"(v) : "r"(addr));
    return v;
}
__device__ __forceinline__ void cp16(uint32_t saddr, const void* gptr) {
    asm volatile("cp.async.cg.shared.global [%0], [%1], 16;"
                 :: "r"(saddr), "l"(gptr));
}
#define CP_COMMIT() asm volatile("cp.async.commit_group;" ::: "memory")
#define CP_WAIT(n)  asm volatile("cp.async.wait_group %0;" :: "n"(n) : "memory")

// ---------------------------------------------------------------------------
// merged fp32 -> fp16 convert for w1 | w2 | x (grid-stride, HBM-bound)
// ---------------------------------------------------------------------------
__global__ __launch_bounds__(256) void k_cvt_all(
    const float4* __restrict__ w1, const float4* __restrict__ w2,
    const float4* __restrict__ x,
    uint2* __restrict__ w1h, uint2* __restrict__ w2h, uint2* __restrict__ xh)
{
    constexpr int N1 = 3 * Dm * Dm / 4;
    constexpr int N2 = Dm * Dm / 4;
    constexpr int N3 = Bm * Dm / 4;
    const int stride = gridDim.x * 256;
    for (int i = blockIdx.x * 256 + threadIdx.x; i < N1 + N2 + N3; i += stride) {
        const float4* s; uint2* d; int j;
        if (i < N1)            { s = w1; d = w1h; j = i; }
        else if (i < N1 + N2)  { s = w2; d = w2h; j = i - N1; }
        else                   { s = x;  d = xh;  j = i - N1 - N2; }
        float4 v = s[j];
        d[j] = make_uint2(pack_h2(v.x, v.y), pack_h2(v.z, v.w));
    }
}

// ---------------------------------------------------------------------------
// fp16 tensor-core GEMM, cp.async multi-stage: C[M,N] (+)= A[M,K]@Bw[N,K]^T
// PITCH = BK*2+16 keeps ldmatrix + B-frag LDS conflict-free.
// SPLITK>1: blockIdx.z selects K-slab; epilogue uses atomicAdd (C pre-zeroed).
// ---------------------------------------------------------------------------
template <int BM, int BN, int BK, int WM, int WN, int THREADS, int STAGES,
          int SPLITK, int MAXCTA>
__global__ __launch_bounds__(THREADS, MAXCTA) void k_mma_f16cp(
    const __half* __restrict__ A, const __half* __restrict__ Bw,
    float* __restrict__ C, int lda, int ldb, int ldc)
{
    extern __shared__ uint8_t smem[];
    constexpr int ROWS = BM + BN;
    constexpr int PITCH = BK * 2 + 16;
    constexpr int STGB = ROWS * PITCH;
    constexpr int MT = WM / 16, NT = WN / 8;
    constexpr int WARPS_N = BN / WN;
    constexpr int RCH = BK * 2 / 16;
    constexpr int TOTCH = ROWS * RCH;
    constexpr int NCHUNK = (TOTCH + THREADS - 1) / THREADS;
    constexpr int KLEN = Dm / SPLITK;
    constexpr int NSTG = KLEN / BK;
    constexpr int KSTEPS = BK / 16;

    const int tid = threadIdx.x;
    const int wid = tid >> 5, lane = tid & 31;
    const int g = lane >> 2, c = lane & 3;
    const int wm = (wid / WARPS_N) * WM, wn = (wid % WARPS_N) * WN;
    const int mBase = blockIdx.y * BM, nBase = blockIdx.x * BN;
    const int kBase = blockIdx.z * KLEN;

    const uint32_t sbase = (uint32_t)__cvta_generic_to_shared(smem);

    const int lr = lane & 7, mat = lane >> 3;
    uint32_t aoff[MT];
    #pragma unroll
    for (int mt = 0; mt < MT; mt++)
        aoff[mt] = (uint32_t)(wm + mt * 16 + lr + (mat & 1) * 8) * PITCH
                 + (uint32_t)(mat >> 1) * 16;
    uint32_t boff[NT];
    #pragma unroll
    for (int nt = 0; nt < NT; nt++)
        boff[nt] = (uint32_t)(BM + wn + nt * 8 + g) * PITCH + c * 4;

    float acc[MT][NT][4] = {};

    auto load_stage = [&](int s, int k0) {   // k0 in halves (absolute)
        #pragma unroll
        for (int i = 0; i < NCHUNK; i++) {
            int idx = tid + i * THREADS;
            if (TOTCH % THREADS != 0 && idx >= TOTCH) break;
            int row = idx / RCH, ch = idx % RCH;
            const __half* gptr = (row < BM)
                ? &A[(size_t)(mBase + row) * lda + k0 + ch * 8]
                : &Bw[(size_t)(nBase + row - BM) * ldb + k0 + ch * 8];
            cp16(sbase + s * STGB + (uint32_t)row * PITCH + ch * 16, gptr);
        }
    };

    #pragma unroll
    for (int s = 0; s < STAGES - 1; s++) {
        load_stage(s, kBase + s * BK); CP_COMMIT();
    }

    for (int s = 0; s < NSTG; s++) {
        CP_WAIT(STAGES - 2);
        __syncthreads();

        const int nxt = s + STAGES - 1;
        if (nxt < NSTG) load_stage(nxt % STAGES, kBase + nxt * BK);
        CP_COMMIT();

        const uint32_t sb = sbase + (s % STAGES) * STGB;
        #pragma unroll
        for (int step = 0; step < KSTEPS; step++) {
            const uint32_t kb = step * 32;
            uint32_t af[MT][4], bf[NT][2];
            #pragma unroll
            for (int mt = 0; mt < MT; mt++)
                ldsm4(af[mt], sb + aoff[mt] + kb);
            #pragma unroll
            for (int nt = 0; nt < NT; nt++) {
                bf[nt][0] = lds32(sb + boff[nt] + kb);
                bf[nt][1] = lds32(sb + boff[nt] + kb + 16);
            }
            #pragma unroll
            for (int mt = 0; mt < MT; mt++)
                #pragma unroll
                for (int nt = 0; nt < NT; nt++)
                    mma16(acc[mt][nt], af[mt], bf[nt]);
        }
    }

    #pragma unroll
    for (int mt = 0; mt < MT; mt++) {
        const int row = mBase + wm + mt * 16 + g;
        #pragma unroll
        for (int nt = 0; nt < NT; nt++) {
            const int col = nBase + wn + nt * 8 + 2 * c;
            if (SPLITK == 1) {
                *reinterpret_cast<float2*>(&C[(size_t)row * ldc + col]) =
                    make_float2(acc[mt][nt][0], acc[mt][nt][1]);
                *reinterpret_cast<float2*>(&C[(size_t)(row + 8) * ldc + col]) =
                    make_float2(acc[mt][nt][2], acc[mt][nt][3]);
            } else {
                atomicAdd(&C[(size_t)row * ldc + col],       acc[mt][nt][0]);
                atomicAdd(&C[(size_t)row * ldc + col + 1],   acc[mt][nt][1]);
                atomicAdd(&C[(size_t)(row + 8) * ldc + col],     acc[mt][nt][2]);
                atomicAdd(&C[(size_t)(row + 8) * ldc + col + 1], acc[mt][nt][3]);
            }
        }
    }
}

// ---------------------------------------------------------------------------
// Elementwise: gates + cache roll/scatter + depthwise conv + C-gate.
// Emits y as fp16; also zero-inits `out` for GEMM2's atomic split-K epilogue.
// ---------------------------------------------------------------------------
__global__ __launch_bounds__(256) void k_elem(
    const float* __restrict__ conv_cache, const float* __restrict__ conv_w,
    const int* __restrict__ pos_ids, float* __restrict__ out_state,
    float* __restrict__ out)
{
    const int idx = blockIdx.x * 256 + threadIdx.x;   // b*2048 + d
    const int b = idx >> 11, d = idx & 2047;

    const float Bg = g_bcx[(size_t)b * 6144 + d];
    const float Cg = g_bcx[(size_t)b * 6144 + 2048 + d];
    const float xg = g_bcx[(size_t)b * 6144 + 4096 + d];
    const float Bx = Bg * xg;

    int pos = pos_ids[0];
    pos = min(max(pos, 0), 3);

    const float4 cc = *reinterpret_cast<const float4*>(conv_cache + (size_t)idx * 4);
    float st[4] = {cc.y, cc.z, cc.w, cc.x};   // roll left by 1
    st[pos] = Bx;

    const float4 cw = *reinterpret_cast<const float4*>(conv_w + (size_t)d * 4);
    const float co = st[0] * cw.x + st[1] * cw.y + st[2] * cw.z + st[3] * cw.w;

    g_yh[idx] = __float2half(Cg * co);
    out[idx] = 0.0f;                          // zero-init for split-K atomics
    *reinterpret_cast<float4*>(out_state + (size_t)idx * 4) =
        make_float4(st[0], st[1], st[2], st[3]);
}

// ---------------------------------------------------------------------------
extern "C" void kernel_launch(void* const* d_in, const int* in_sizes, int n_in,
                              void* d_out, int out_size) {
    const float* x          = (const float*)d_in[0];
    const float* conv_cache = (const float*)d_in[1];
    const float* w1         = (const float*)d_in[2];
    const float* w2         = (const float*)d_in[3];
    const float* conv_w     = (const float*)d_in[4];
    const int*   pos_ids    = (const int*)d_in[5];

    float* out       = (float*)d_out;            // [B,1,D]
    float* out_state = out + (size_t)Bm * Dm;    // [B,D,K]

    float* bcx = nullptr;
    __half *w1h = nullptr, *w2h = nullptr, *xh = nullptr, *yh = nullptr;
    cudaGetSymbolAddress((void**)&bcx, g_bcx);
    cudaGetSymbolAddress((void**)&w1h, g_w1h);
    cudaGetSymbolAddress((void**)&w2h, g_w2h);
    cudaGetSymbolAddress((void**)&xh, g_xh);
    cudaGetSymbolAddress((void**)&yh, g_yh);

    // merged fp32 -> fp16 converts (one launch, grid-stride)
    k_cvt_all<<<2048, 256>>>((const float4*)w1, (const float4*)w2,
                             (const float4*)x,
                             (uint2*)w1h, (uint2*)w2h, (uint2*)xh);

    // GEMM1: 64x96, BK=64, 6 warps (32x32), 4 stages, 2 CTAs/SM
    // smem = 4 * 160 * 144 = 92160 B; grid = 64 x 4 = 256 CTAs
    constexpr int SMEM1 = 4 * (64 + 96) * 144;
    // GEMM2: 64x64, BK=64, 8 warps (32x16), 3 stages, split-K=2, 2 CTAs/SM
    // smem = 3 * 128 * 144 = 55296 B; grid = 32 x 4 x 2 = 256 CTAs
    constexpr int SMEM2 = 3 * (64 + 64) * 144;
    cudaFuncSetAttribute((const void*)k_mma_f16cp<64, 96, 64, 32, 32, 192, 4, 1, 2>,
                         cudaFuncAttributeMaxDynamicSharedMemorySize, SMEM1);
    cudaFuncSetAttribute((const void*)k_mma_f16cp<64, 64, 64, 32, 16, 256, 3, 2, 2>,
                         cudaFuncAttributeMaxDynamicSharedMemorySize, SMEM2);

    // GEMM1: BCx[256, 6144] = x[256,2048] @ w1[6144,2048]^T
    k_mma_f16cp<64, 96, 64, 32, 32, 192, 4, 1, 2>
        <<<dim3(3 * Dm / 96, Bm / 64), 192, SMEM1>>>(xh, w1h, bcx, Dm, Dm, 3 * Dm);

    // gating + conv + state scatter (+ zero-init out)
    k_elem<<<(Bm * Dm) / 256, 256>>>(conv_cache, conv_w, pos_ids, out_state, out);

    // GEMM2: out[256, 2048] += y[256,2048] @ w2[2048,2048]^T  (split-K=2)
    k_mma_f16cp<64, 64, 64, 32, 16, 256, 3, 2, 2>
        <<<dim3(Dm / 64, Bm / 64, 2), 256, SMEM2>>>(yh, w2h, out, Dm, Dm, Dm);
}